// round 13
// baseline (speedup 1.0000x reference)
#include <cuda_runtime.h>
#include <cstdint>

// ---------------------------------------------------------------------------
// DoseEncoder — register-lean warp-autonomous j-packed f32x2 kernel.
//  (tcgen05 unavailable: harness ptxas targets sm_103, not sm_103a)
//
//  * 3-kernel pipeline: dtlast (binary search) -> main -> combine.
//  * main: grid (T/64, 4). Block = 128 thr; warp w owns 16 t over the
//    block's 64 doses (2/thread). NO barriers in the main loop.
//  * All weights/biases for layers 1-3 prescaled by 0.5 so every
//    pre-activation is y = x/2 and silu(x) = y + y*tanh(y) = 1 fma2/pair.
//  * Layer-2 output (h2) self-spilled packed to SMEM (thread-private,
//    warp-synchronous) so acc2 and acc3 are never both register-live:
//    peak regs ~90 -> __launch_bounds__(128,4) = 4 CTAs/SM.
// ---------------------------------------------------------------------------

#define TPB   128
#define T_MAX 32768

typedef unsigned long long ull;

__device__ float g_dtlast[T_MAX];
__device__ float g_part[4 * T_MAX];

// dynamic smem layout (byte offsets, all 16B-aligned)
#define OFF_W2   0        // ull[32][16]  0.5*W2 j-packed, row 128B   (4 KB)
#define OFF_W3   4096     // ull[32][16]                              (4 KB)
#define OFF_V    8192     // ull[32][32]  [i][lane] {0.5*VA_i,0.5*VB_i} (8 KB)
#define OFF_HA   16384    // ull[4][16][32]  h2 doseA packed          (16 KB)
#define OFF_HB   32768    // ull[4][16][32]  h2 doseB packed          (16 KB)
#define OFF_W1TD 49152    // ull[32]  dup{0.5*W1t_i}
#define OFF_W1DD 49408    // ull[32]  dup{0.5*W1dl_i}
#define OFF_B2   49664    // ull[16]  {0.5*b2_2j, 0.5*b2_2j+1}
#define OFF_B3   49792
#define OFF_W4   49920    // ull[16]  {w4_2j, w4_2j+1}  (UNscaled)
#define SMEM_DYN 50048

// ---- packed f32x2 helpers --------------------------------------------------
__device__ __forceinline__ ull packf2(float a, float b) {
    ull r; asm("mov.b64 %0, {%1, %2};" : "=l"(r) : "f"(a), "f"(b)); return r;
}
__device__ __forceinline__ void unpackf2(ull x, float& a, float& b) {
    asm("mov.b64 {%0, %1}, %2;" : "=f"(a), "=f"(b) : "l"(x));
}
__device__ __forceinline__ ull dupf(float a) {
    ull r; asm("mov.b64 %0, {%1, %1};" : "=l"(r) : "f"(a)); return r;
}
__device__ __forceinline__ ull fma2u(ull a, ull b, ull c) {
    ull r; asm("fma.rn.f32x2 %0, %1, %2, %3;" : "=l"(r) : "l"(a), "l"(b), "l"(c));
    return r;
}
__device__ __forceinline__ float ex2f(float x) {
    float r; asm("ex2.approx.f32 %0, %1;" : "=f"(r) : "f"(x)); return r;
}
__device__ __forceinline__ float tanhf_(float x) {
    float r; asm("tanh.approx.f32 %0, %1;" : "=f"(r) : "f"(x)); return r;
}
// input y = x/2 (prescaled). silu(x) = y + y*tanh(y), both lanes. 1 fma2.
__device__ __forceinline__ ull silup(ull y) {
    float y0, y1; unpackf2(y, y0, y1);
    float t0 = tanhf_(y0), t1 = tanhf_(y1);
    return fma2u(y, packf2(t0, t1), y);
}

// ---------------------------------------------------------------------------
// Kernel 1: dt_last via binary search (doses sorted ascending).
// ---------------------------------------------------------------------------
__global__ void dtlast_kernel(const float* __restrict__ t_abs,
                              const float* __restrict__ dose_t,
                              const float* __restrict__ span_p,
                              int T, int D) {
    int i = blockIdx.x * blockDim.x + threadIdx.x;
    if (i >= T) return;
    float ta = t_abs[i];
    float inv_span = 1.0f / span_p[0];
    int pos = 0;
#pragma unroll
    for (int s = 256; s > 0; s >>= 1) {
        int np = pos + s;
        if (np <= D && dose_t[np - 1] <= ta) pos = np;
    }
    g_dtlast[i] = (pos > 0) ? (ta - dose_t[pos - 1]) * inv_span
                            : __int_as_float(0x7f800000);
}

// ---------------------------------------------------------------------------
// Kernel 2: main. grid = (T/64, 4) x 128 threads.
// ---------------------------------------------------------------------------
__global__ void __launch_bounds__(TPB, 4)
dose_encoder_kernel(const float* __restrict__ t_abs,
                    const float* __restrict__ dose_t,
                    const float* __restrict__ amts,
                    const float* __restrict__ ss,
                    const float* __restrict__ ii,
                    const float* __restrict__ span_p,
                    const float* __restrict__ logsig,
                    const float* __restrict__ W1,
                    const float* __restrict__ b1,
                    const float* __restrict__ W2,
                    const float* __restrict__ b2,
                    const float* __restrict__ W3,
                    const float* __restrict__ b3,
                    const float* __restrict__ W4,
                    const float* __restrict__ b4,
                    int T) {
    extern __shared__ char sm[];
    ull* W2p  = (ull*)(sm + OFF_W2);
    ull* W3p  = (ull*)(sm + OFF_W3);
    ull* Vab  = (ull*)(sm + OFF_V);
    ull* W1Td = (ull*)(sm + OFF_W1TD);
    ull* W1Dd = (ull*)(sm + OFF_W1DD);
    ull* B2p  = (ull*)(sm + OFF_B2);
    ull* B3p  = (ull*)(sm + OFF_B3);
    ull* W4p  = (ull*)(sm + OFF_W4);

    const int tid  = threadIdx.x;
    const int lane = tid & 31;
    const int warp = tid >> 5;
    const int q    = blockIdx.y;
    const int dq0  = q * 64;

    const float span     = span_p[0];
    const float inv_span = 1.0f / span;
    const float sigma    = expf(logsig[0]);
    const float wc_l2    = -0.5f / (sigma * sigma) * 1.4426950408889634f;
    const float b4v      = b4[0];

    // ---- prolog: prescaled weight staging ----
    for (int idx = tid; idx < 512; idx += TPB) {
        int i = idx >> 4, jp = idx & 15;
        W2p[idx] = packf2(0.5f * W2[i * 32 + 2 * jp], 0.5f * W2[i * 32 + 2 * jp + 1]);
        W3p[idx] = packf2(0.5f * W3[i * 32 + 2 * jp], 0.5f * W3[i * 32 + 2 * jp + 1]);
    }
    if (tid < 32) {
        W1Td[tid] = dupf(0.5f * W1[tid]);
        W1Dd[tid] = dupf(0.5f * W1[64 + tid]);
    }
    if (tid < 16) {
        B2p[tid] = packf2(0.5f * b2[2 * tid], 0.5f * b2[2 * tid + 1]);
        B3p[tid] = packf2(0.5f * b3[2 * tid], 0.5f * b3[2 * tid + 1]);
        W4p[tid] = packf2(W4[2 * tid], W4[2 * tid + 1]);
    }

    // ---- V vectors (prescaled, incl. 0.5*b1): thread fills 8 i-rows ----
    {
        int l  = tid & 31;
        int i0 = (tid >> 5) * 8;
        int da = dq0 + 2 * l, db = da + 1;
        float dnA = dose_t[da] * inv_span, dnB = dose_t[db] * inv_span;
        float laA = log1pf(amts[da]),      laB = log1pf(amts[db]);
        float spe = 1.0f / (span + 1e-6f);
        float ssA = ss[da] * spe, ssB = ss[db] * spe;
        float iiA = ii[da] * spe, iiB = ii[db] * spe;
        for (int i = i0; i < i0 + 8; i++) {
            float wdt = W1[i], wla = W1[32 + i];
            float wss = W1[96 + i], wii = W1[128 + i];
            float bb  = b1[i];
            float vA = fmaf(-dnA, wdt, fmaf(laA, wla, fmaf(ssA, wss, fmaf(iiA, wii, bb))));
            float vB = fmaf(-dnB, wdt, fmaf(laB, wla, fmaf(ssB, wss, fmaf(iiB, wii, bb))));
            Vab[i * 32 + l] = packf2(0.5f * vA, 0.5f * vB);
        }
    }
    __syncthreads();   // the ONLY block barrier

    const int dA = dq0 + 2 * lane, dB = dA + 1;
    const float dnA = dose_t[dA] * inv_span;
    const float dnB = dose_t[dB] * inv_span;

    const unsigned smb    = (unsigned)__cvta_generic_to_shared(sm);
    const unsigned w2base = smb + OFF_W2;
    const unsigned w3base = smb + OFF_W3;
    ull* HsA = (ull*)(sm + OFF_HA) + warp * 512;   // [k][lane]
    ull* HsB = (ull*)(sm + OFF_HB) + warp * 512;

    const int tbase = blockIdx.x * 64 + warp * 16;
    float* __restrict__ part_out = g_part + q * T_MAX;

#pragma unroll 1
    for (int g = 0; g < 16; g++) {
        int tt = tbase + g;
        if (tt >= T) break;
        float tnorm = t_abs[tt] * inv_span;
        float dl    = g_dtlast[tt];
        ull tn2 = dupf(tnorm);
        ull dl2 = dupf(dl);

        // ---- layer 1 fused into layer-2 accumulation ----
        ull accA[16], accB[16];
#pragma unroll
        for (int jp = 0; jp < 16; jp++) { ull bb = B2p[jp]; accA[jp] = bb; accB[jp] = bb; }

#pragma unroll 4
        for (int i = 0; i < 32; i++) {
            ull pre = fma2u(tn2, W1Td[i], fma2u(dl2, W1Dd[i], Vab[i * 32 + lane]));
            ull h   = silup(pre);                 // {h1A_i, h1B_i}
            float hA, hB; unpackf2(h, hA, hB);
            ull dAu = dupf(hA), dBu = dupf(hB);
            unsigned rb = w2base + (unsigned)i * 128;
#pragma unroll
            for (int jp = 0; jp < 16; jp += 2) {
                ull w0, w1;
                asm("ld.shared.v2.u64 {%0, %1}, [%2];"
                    : "=l"(w0), "=l"(w1) : "r"(rb + jp * 8));
                accA[jp]     = fma2u(dAu, w0, accA[jp]);
                accA[jp + 1] = fma2u(dAu, w1, accA[jp + 1]);
                accB[jp]     = fma2u(dBu, w0, accB[jp]);
                accB[jp + 1] = fma2u(dBu, w1, accB[jp + 1]);
            }
        }

        // ---- mid silu -> SMEM spill (packed, thread-private) ----
#pragma unroll
        for (int k = 0; k < 16; k++) {
            HsA[k * 32 + lane] = silup(accA[k]);
            HsB[k * 32 + lane] = silup(accB[k]);
        }

        // ---- layer 3 (h2 from SMEM, acc2 regs now dead) ----
        ull a3A[16], a3B[16];
#pragma unroll
        for (int jp = 0; jp < 16; jp++) { ull bb = B3p[jp]; a3A[jp] = bb; a3B[jp] = bb; }

#pragma unroll 2
        for (int k = 0; k < 16; k++) {
            ull h2a = HsA[k * 32 + lane];
            ull h2b = HsB[k * 32 + lane];
            float a0, a1, b0, b1v;
            unpackf2(h2a, a0, a1);
            unpackf2(h2b, b0, b1v);
            {   // i = 2k
                ull dAu = dupf(a0), dBu = dupf(b0);
                unsigned rb = w3base + (unsigned)(2 * k) * 128;
#pragma unroll
                for (int jp = 0; jp < 16; jp += 2) {
                    ull w0, w1;
                    asm("ld.shared.v2.u64 {%0, %1}, [%2];"
                        : "=l"(w0), "=l"(w1) : "r"(rb + jp * 8));
                    a3A[jp]     = fma2u(dAu, w0, a3A[jp]);
                    a3A[jp + 1] = fma2u(dAu, w1, a3A[jp + 1]);
                    a3B[jp]     = fma2u(dBu, w0, a3B[jp]);
                    a3B[jp + 1] = fma2u(dBu, w1, a3B[jp + 1]);
                }
            }
            {   // i = 2k+1
                ull dAu = dupf(a1), dBu = dupf(b1v);
                unsigned rb = w3base + (unsigned)(2 * k + 1) * 128;
#pragma unroll
                for (int jp = 0; jp < 16; jp += 2) {
                    ull w0, w1;
                    asm("ld.shared.v2.u64 {%0, %1}, [%2];"
                        : "=l"(w0), "=l"(w1) : "r"(rb + jp * 8));
                    a3A[jp]     = fma2u(dAu, w0, a3A[jp]);
                    a3A[jp + 1] = fma2u(dAu, w1, a3A[jp + 1]);
                    a3B[jp]     = fma2u(dBu, w0, a3B[jp]);
                    a3B[jp + 1] = fma2u(dBu, w1, a3B[jp + 1]);
                }
            }
        }

        // ---- layer 4: silu packed + dot W4 ----
        ull sA = packf2(0.0f, 0.0f), sB = sA;
#pragma unroll
        for (int jp = 0; jp < 16; jp++) {
            ull w4 = W4p[jp];
            sA = fma2u(silup(a3A[jp]), w4, sA);
            sB = fma2u(silup(a3B[jp]), w4, sB);
        }
        float sa0, sa1, sb0, sb1;
        unpackf2(sA, sa0, sa1);
        unpackf2(sB, sb0, sb1);
        float scoreA = sa0 + sa1 + b4v;
        float scoreB = sb0 + sb1 + b4v;

        // ---- gaussian weight + masked warp reduce over 64 doses ----
        float dtA = tnorm - dnA;
        float dtB = tnorm - dnB;
        float wA = (dtA >= 0.0f) ? ex2f(wc_l2 * dtA * dtA) : 0.0f;
        float wB = (dtB >= 0.0f) ? ex2f(wc_l2 * dtB * dtB) : 0.0f;
        float part = scoreA * wA + scoreB * wB;
#pragma unroll
        for (int off = 16; off > 0; off >>= 1)
            part += __shfl_xor_sync(0xffffffffu, part, off);
        if (lane == 0) part_out[tt] = part;
    }
}

// ---------------------------------------------------------------------------
// Kernel 3: combine quarter partials (deterministic).
// ---------------------------------------------------------------------------
__global__ void combine_kernel(float* __restrict__ out, int T) {
    int i = blockIdx.x * blockDim.x + threadIdx.x;
    if (i >= T) return;
    float p0 = g_part[0 * T_MAX + i];
    float p1 = g_part[1 * T_MAX + i];
    float p2 = g_part[2 * T_MAX + i];
    float p3 = g_part[3 * T_MAX + i];
    out[i] = (p0 + p1) + (p2 + p3);
}

extern "C" void kernel_launch(void* const* d_in, const int* in_sizes, int n_in,
                              void* d_out, int out_size) {
    const float* t_abs  = (const float*)d_in[0];
    const float* dose_t = (const float*)d_in[1];
    const float* amts   = (const float*)d_in[2];
    const float* ss     = (const float*)d_in[3];
    const float* ii     = (const float*)d_in[4];
    const float* span_p = (const float*)d_in[5];
    const float* logsig = (const float*)d_in[6];
    const float* W1     = (const float*)d_in[7];
    const float* b1     = (const float*)d_in[8];
    const float* W2     = (const float*)d_in[9];
    const float* b2     = (const float*)d_in[10];
    const float* W3     = (const float*)d_in[11];
    const float* b3     = (const float*)d_in[12];
    const float* W4     = (const float*)d_in[13];
    const float* b4     = (const float*)d_in[14];
    float* out = (float*)d_out;
    const int T = in_sizes[0];
    const int D = in_sizes[1];

    cudaFuncSetAttribute(dose_encoder_kernel,
                         cudaFuncAttributeMaxDynamicSharedMemorySize, SMEM_DYN);

    dtlast_kernel<<<(T + 255) / 256, 256>>>(t_abs, dose_t, span_p, T, D);

    dim3 grid((T + 63) / 64, 4);
    dose_encoder_kernel<<<grid, TPB, SMEM_DYN>>>(
        t_abs, dose_t, amts, ss, ii, span_p, logsig,
        W1, b1, W2, b2, W3, b3, W4, b4, T);

    combine_kernel<<<(T + 255) / 256, 256>>>(out, T);
}

// round 14
// speedup vs baseline: 1.0249x; 1.0249x over previous
#include <cuda_runtime.h>
#include <cstdint>

// ---------------------------------------------------------------------------
// DoseEncoder — warp-autonomous j-packed f32x2, 4-CTA register budget.
//
//  * 3-kernel pipeline: dtlast (binary search) -> main -> combine.
//  * main: grid (T/64, 4). Block = 128 thr; warp w owns 16 t over the
//    block's 64 doses (2/thread, f32x2 lanes = hidden-j pairs).
//    NO barriers in the main loop.
//  * Prescale-by-0.5 on layers 1-3 so silu(x) = y + y*tanh(y), y arrives
//    as x/2: one fma2 + two MUFU.TANH per packed pair.
//  * Register plan (target peak ~116, under the 128 needed for 4 CTAs/SM):
//      layer2: acc2 64 regs, h1 transient
//      layer3: h2 64 regs + HALF accumulators 32 regs (two jp-half passes,
//              each half silu'd + dotted with W4 immediately, then dies)
// ---------------------------------------------------------------------------

#define TPB   128
#define T_MAX 32768

typedef unsigned long long ull;

__device__ float g_dtlast[T_MAX];
__device__ float g_part[4 * T_MAX];

// dynamic smem layout (byte offsets)
#define OFF_W2   0        // ull[32][16]  0.5*W2 j-packed, 128B rows  (4 KB)
#define OFF_W3   4096     // ull[32][16]                              (4 KB)
#define OFF_V    8192     // ull[32][32]  [i][lane] {0.5*VA_i, 0.5*VB_i} (8 KB)
#define OFF_W1TD 16384    // ull[32]  dup{0.5*W1t_i}
#define OFF_W1DD 16640    // ull[32]  dup{0.5*W1dl_i}
#define OFF_B2   16896    // ull[16]  {0.5*b2}j-packed
#define OFF_B3   17024
#define OFF_W4   17152    // ull[16]  {w4} j-packed (UNscaled)
#define SMEM_DYN 17280

// ---- packed f32x2 helpers --------------------------------------------------
__device__ __forceinline__ ull packf2(float a, float b) {
    ull r; asm("mov.b64 %0, {%1, %2};" : "=l"(r) : "f"(a), "f"(b)); return r;
}
__device__ __forceinline__ void unpackf2(ull x, float& a, float& b) {
    asm("mov.b64 {%0, %1}, %2;" : "=f"(a), "=f"(b) : "l"(x));
}
__device__ __forceinline__ ull dupf(float a) {
    ull r; asm("mov.b64 %0, {%1, %1};" : "=l"(r) : "f"(a)); return r;
}
__device__ __forceinline__ ull fma2u(ull a, ull b, ull c) {
    ull r; asm("fma.rn.f32x2 %0, %1, %2, %3;" : "=l"(r) : "l"(a), "l"(b), "l"(c));
    return r;
}
__device__ __forceinline__ float ex2f(float x) {
    float r; asm("ex2.approx.f32 %0, %1;" : "=f"(r) : "f"(x)); return r;
}
__device__ __forceinline__ float tanhf_(float x) {
    float r; asm("tanh.approx.f32 %0, %1;" : "=f"(r) : "f"(x)); return r;
}
// input y = x/2 (prescaled). silu(x) = y + y*tanh(y), both lanes.
__device__ __forceinline__ ull silup(ull y) {
    float y0, y1; unpackf2(y, y0, y1);
    float t0 = tanhf_(y0), t1 = tanhf_(y1);
    return fma2u(y, packf2(t0, t1), y);
}

// ---------------------------------------------------------------------------
// Kernel 1: dt_last via binary search (doses sorted ascending).
// ---------------------------------------------------------------------------
__global__ void dtlast_kernel(const float* __restrict__ t_abs,
                              const float* __restrict__ dose_t,
                              const float* __restrict__ span_p,
                              int T, int D) {
    int i = blockIdx.x * blockDim.x + threadIdx.x;
    if (i >= T) return;
    float ta = t_abs[i];
    float inv_span = 1.0f / span_p[0];
    int pos = 0;
#pragma unroll
    for (int s = 256; s > 0; s >>= 1) {
        int np = pos + s;
        if (np <= D && dose_t[np - 1] <= ta) pos = np;
    }
    g_dtlast[i] = (pos > 0) ? (ta - dose_t[pos - 1]) * inv_span
                            : __int_as_float(0x7f800000);
}

// ---------------------------------------------------------------------------
// Kernel 2: main. grid = (T/64, 4) x 128 threads.
// ---------------------------------------------------------------------------
__global__ void __launch_bounds__(TPB, 4)
dose_encoder_kernel(const float* __restrict__ t_abs,
                    const float* __restrict__ dose_t,
                    const float* __restrict__ amts,
                    const float* __restrict__ ss,
                    const float* __restrict__ ii,
                    const float* __restrict__ span_p,
                    const float* __restrict__ logsig,
                    const float* __restrict__ W1,
                    const float* __restrict__ b1,
                    const float* __restrict__ W2,
                    const float* __restrict__ b2,
                    const float* __restrict__ W3,
                    const float* __restrict__ b3,
                    const float* __restrict__ W4,
                    const float* __restrict__ b4,
                    int T) {
    extern __shared__ char sm[];
    ull* W2p  = (ull*)(sm + OFF_W2);
    ull* W3p  = (ull*)(sm + OFF_W3);
    ull* Vab  = (ull*)(sm + OFF_V);
    ull* W1Td = (ull*)(sm + OFF_W1TD);
    ull* W1Dd = (ull*)(sm + OFF_W1DD);
    ull* B2p  = (ull*)(sm + OFF_B2);
    ull* B3p  = (ull*)(sm + OFF_B3);
    ull* W4p  = (ull*)(sm + OFF_W4);

    const int tid  = threadIdx.x;
    const int lane = tid & 31;
    const int warp = tid >> 5;
    const int q    = blockIdx.y;
    const int dq0  = q * 64;

    const float span     = span_p[0];
    const float inv_span = 1.0f / span;
    const float sigma    = expf(logsig[0]);
    const float wc_l2    = -0.5f / (sigma * sigma) * 1.4426950408889634f;
    const float b4v      = b4[0];

    // ---- prolog: prescaled weight staging ----
    for (int idx = tid; idx < 512; idx += TPB) {
        int i = idx >> 4, jp = idx & 15;
        W2p[idx] = packf2(0.5f * W2[i * 32 + 2 * jp], 0.5f * W2[i * 32 + 2 * jp + 1]);
        W3p[idx] = packf2(0.5f * W3[i * 32 + 2 * jp], 0.5f * W3[i * 32 + 2 * jp + 1]);
    }
    if (tid < 32) {
        W1Td[tid] = dupf(0.5f * W1[tid]);
        W1Dd[tid] = dupf(0.5f * W1[64 + tid]);
    }
    if (tid < 16) {
        B2p[tid] = packf2(0.5f * b2[2 * tid], 0.5f * b2[2 * tid + 1]);
        B3p[tid] = packf2(0.5f * b3[2 * tid], 0.5f * b3[2 * tid + 1]);
        W4p[tid] = packf2(W4[2 * tid], W4[2 * tid + 1]);
    }

    // ---- V vectors (prescaled, incl. 0.5*b1): warp w fills i-rows 8w..8w+7 ----
    {
        int l  = lane;
        int i0 = warp * 8;
        int da = dq0 + 2 * l, db = da + 1;
        float dnAx = dose_t[da] * inv_span, dnBx = dose_t[db] * inv_span;
        float laA = log1pf(amts[da]),       laB = log1pf(amts[db]);
        float spe = 1.0f / (span + 1e-6f);
        float ssA = ss[da] * spe, ssB = ss[db] * spe;
        float iiA = ii[da] * spe, iiB = ii[db] * spe;
        for (int i = i0; i < i0 + 8; i++) {
            float wdt = W1[i], wla = W1[32 + i];
            float wss = W1[96 + i], wii = W1[128 + i];
            float bb  = b1[i];
            float vA = fmaf(-dnAx, wdt, fmaf(laA, wla, fmaf(ssA, wss, fmaf(iiA, wii, bb))));
            float vB = fmaf(-dnBx, wdt, fmaf(laB, wla, fmaf(ssB, wss, fmaf(iiB, wii, bb))));
            Vab[i * 32 + l] = packf2(0.5f * vA, 0.5f * vB);
        }
    }
    __syncthreads();   // the ONLY block barrier

    const int dA = dq0 + 2 * lane, dB = dA + 1;
    const float dnA = dose_t[dA] * inv_span;
    const float dnB = dose_t[dB] * inv_span;

    const unsigned smb    = (unsigned)__cvta_generic_to_shared(sm);
    const unsigned w2base = smb + OFF_W2;
    const unsigned w3base = smb + OFF_W3;

    const int tbase = blockIdx.x * 64 + warp * 16;
    float* __restrict__ part_out = g_part + q * T_MAX;

#pragma unroll 1
    for (int g = 0; g < 16; g++) {
        int tt = tbase + g;
        if (tt >= T) break;
        float tnorm = t_abs[tt] * inv_span;
        float dl    = g_dtlast[tt];
        ull tn2 = dupf(tnorm);
        ull dl2 = dupf(dl);

        // ==== layer 2 full-width, layer 1 fused (peak ~90 regs) ====
        ull accA[16], accB[16];
#pragma unroll
        for (int jp = 0; jp < 16; jp++) { ull bb = B2p[jp]; accA[jp] = bb; accB[jp] = bb; }

#pragma unroll 4
        for (int i = 0; i < 32; i++) {
            ull pre = fma2u(tn2, W1Td[i], fma2u(dl2, W1Dd[i], Vab[i * 32 + lane]));
            ull h   = silup(pre);                 // {h1A_i, h1B_i}
            float hA, hB; unpackf2(h, hA, hB);
            ull dAu = dupf(hA), dBu = dupf(hB);
            unsigned rb = w2base + (unsigned)i * 128;
#pragma unroll
            for (int jp = 0; jp < 16; jp += 2) {
                ull w0, w1;
                asm("ld.shared.v2.u64 {%0, %1}, [%2];"
                    : "=l"(w0), "=l"(w1) : "r"(rb + jp * 8));
                accA[jp]     = fma2u(dAu, w0, accA[jp]);
                accA[jp + 1] = fma2u(dAu, w1, accA[jp + 1]);
                accB[jp]     = fma2u(dBu, w0, accB[jp]);
                accB[jp + 1] = fma2u(dBu, w1, accB[jp + 1]);
            }
        }

        // ==== silu in place: acc -> h2 (reuses the same 64 regs) ====
#pragma unroll
        for (int jp = 0; jp < 16; jp++) {
            accA[jp] = silup(accA[jp]);
            accB[jp] = silup(accB[jp]);
        }
        // accA/accB now hold h2 ({h2_2jp, h2_2jp+1} per dose)

        // ==== layer 3 in two jp-half passes (peak ~116 regs) ====
        ull s4A = packf2(0.0f, 0.0f), s4B = s4A;
#pragma unroll
        for (int half = 0; half < 2; half++) {
            ull a3A[8], a3B[8];
#pragma unroll
            for (int jp = 0; jp < 8; jp++) {
                ull bb = B3p[half * 8 + jp];
                a3A[jp] = bb; a3B[jp] = bb;
            }
#pragma unroll 2
            for (int k = 0; k < 16; k++) {
                float a0, a1, b0, b1v;
                unpackf2(accA[k], a0, a1);
                unpackf2(accB[k], b0, b1v);
                {   // i = 2k
                    ull dAu = dupf(a0), dBu = dupf(b0);
                    unsigned rb = w3base + (unsigned)(2 * k) * 128 + half * 64;
#pragma unroll
                    for (int jp = 0; jp < 8; jp += 2) {
                        ull w0, w1;
                        asm("ld.shared.v2.u64 {%0, %1}, [%2];"
                            : "=l"(w0), "=l"(w1) : "r"(rb + jp * 8));
                        a3A[jp]     = fma2u(dAu, w0, a3A[jp]);
                        a3A[jp + 1] = fma2u(dAu, w1, a3A[jp + 1]);
                        a3B[jp]     = fma2u(dBu, w0, a3B[jp]);
                        a3B[jp + 1] = fma2u(dBu, w1, a3B[jp + 1]);
                    }
                }
                {   // i = 2k+1
                    ull dAu = dupf(a1), dBu = dupf(b1v);
                    unsigned rb = w3base + (unsigned)(2 * k + 1) * 128 + half * 64;
#pragma unroll
                    for (int jp = 0; jp < 8; jp += 2) {
                        ull w0, w1;
                        asm("ld.shared.v2.u64 {%0, %1}, [%2];"
                            : "=l"(w0), "=l"(w1) : "r"(rb + jp * 8));
                        a3A[jp]     = fma2u(dAu, w0, a3A[jp]);
                        a3A[jp + 1] = fma2u(dAu, w1, a3A[jp + 1]);
                        a3B[jp]     = fma2u(dBu, w0, a3B[jp]);
                        a3B[jp + 1] = fma2u(dBu, w1, a3B[jp + 1]);
                    }
                }
            }
            // silu + W4 dot for this half (half accumulators die here)
#pragma unroll
            for (int jp = 0; jp < 8; jp++) {
                ull w4 = W4p[half * 8 + jp];
                s4A = fma2u(silup(a3A[jp]), w4, s4A);
                s4B = fma2u(silup(a3B[jp]), w4, s4B);
            }
        }

        float sa0, sa1, sb0, sb1;
        unpackf2(s4A, sa0, sa1);
        unpackf2(s4B, sb0, sb1);
        float scoreA = sa0 + sa1 + b4v;
        float scoreB = sb0 + sb1 + b4v;

        // ---- gaussian weight + masked warp reduce over 64 doses ----
        float dtA = tnorm - dnA;
        float dtB = tnorm - dnB;
        float wA = (dtA >= 0.0f) ? ex2f(wc_l2 * dtA * dtA) : 0.0f;
        float wB = (dtB >= 0.0f) ? ex2f(wc_l2 * dtB * dtB) : 0.0f;
        float part = scoreA * wA + scoreB * wB;
#pragma unroll
        for (int off = 16; off > 0; off >>= 1)
            part += __shfl_xor_sync(0xffffffffu, part, off);
        if (lane == 0) part_out[tt] = part;
    }
}

// ---------------------------------------------------------------------------
// Kernel 3: combine quarter partials (deterministic).
// ---------------------------------------------------------------------------
__global__ void combine_kernel(float* __restrict__ out, int T) {
    int i = blockIdx.x * blockDim.x + threadIdx.x;
    if (i >= T) return;
    float p0 = g_part[0 * T_MAX + i];
    float p1 = g_part[1 * T_MAX + i];
    float p2 = g_part[2 * T_MAX + i];
    float p3 = g_part[3 * T_MAX + i];
    out[i] = (p0 + p1) + (p2 + p3);
}

extern "C" void kernel_launch(void* const* d_in, const int* in_sizes, int n_in,
                              void* d_out, int out_size) {
    const float* t_abs  = (const float*)d_in[0];
    const float* dose_t = (const float*)d_in[1];
    const float* amts   = (const float*)d_in[2];
    const float* ss     = (const float*)d_in[3];
    const float* ii     = (const float*)d_in[4];
    const float* span_p = (const float*)d_in[5];
    const float* logsig = (const float*)d_in[6];
    const float* W1     = (const float*)d_in[7];
    const float* b1     = (const float*)d_in[8];
    const float* W2     = (const float*)d_in[9];
    const float* b2     = (const float*)d_in[10];
    const float* W3     = (const float*)d_in[11];
    const float* b3     = (const float*)d_in[12];
    const float* W4     = (const float*)d_in[13];
    const float* b4     = (const float*)d_in[14];
    float* out = (float*)d_out;
    const int T = in_sizes[0];
    const int D = in_sizes[1];

    cudaFuncSetAttribute(dose_encoder_kernel,
                         cudaFuncAttributeMaxDynamicSharedMemorySize, SMEM_DYN);

    dtlast_kernel<<<(T + 255) / 256, 256>>>(t_abs, dose_t, span_p, T, D);

    dim3 grid((T + 63) / 64, 4);
    dose_encoder_kernel<<<grid, TPB, SMEM_DYN>>>(
        t_abs, dose_t, amts, ss, ii, span_p, logsig,
        W1, b1, W2, b2, W3, b3, W4, b4, T);

    combine_kernel<<<(T + 255) / 256, 256>>>(out, T);
}